// round 2
// baseline (speedup 1.0000x reference)
#include <cuda_runtime.h>

#define L   8192
#define F   9
#define NT  1024
#define CH  (L / NT)   // 8 elements per thread

__device__ __forceinline__ float adjv(float v) {
    // v + 1 - (v > EPS)
    return (v > 1e-13f) ? v : (v + 1.0f);
}

__device__ __forceinline__ float clip01(float x) {
    return fminf(fmaxf(x, 0.0f), 0.9999f);
}

// In-place inclusive block prefix scan of arr[0..L-1] with an initial offset add0.
// Thread t owns the contiguous chunk [t*CH, t*CH+CH). Caller must __syncthreads()
// before (data ready) and after (results visible).
__device__ __forceinline__ void block_scan(float* arr, float* wred, float add0) {
    const int tid  = threadIdx.x;
    const int lane = tid & 31;
    const int wid  = tid >> 5;
    const int base = tid * CH;

    float v[CH];
    float run = 0.0f;
#pragma unroll
    for (int j = 0; j < CH; j++) { run += arr[base + j]; v[j] = run; }

    // inclusive warp scan of per-thread totals
    float x = run;
#pragma unroll
    for (int d = 1; d < 32; d <<= 1) {
        float y = __shfl_up_sync(0xFFFFFFFFu, x, d);
        if (lane >= d) x += y;
    }
    if (lane == 31) wred[wid] = x;
    __syncthreads();
    if (wid == 0) {
        float w = wred[lane];  // 32 warps exactly
#pragma unroll
        for (int d = 1; d < 32; d <<= 1) {
            float y = __shfl_up_sync(0xFFFFFFFFu, w, d);
            if (lane >= d) w += y;
        }
        wred[lane] = w;
    }
    __syncthreads();
    float off = add0 + (x - run) + (wid > 0 ? wred[wid - 1] : 0.0f);
#pragma unroll
    for (int j = 0; j < CH; j++) arr[base + j] = off + v[j];
}

__global__ __launch_bounds__(NT, 1)
void kenneth_kernel(const float* __restrict__ conc,
                    const float* __restrict__ kern,
                    float* __restrict__ out) {
    extern __shared__ float sm[];
    float* sb = sm;            // bcd[t]
    float* sp = sm + L;        // rowsum -> P (1 + inclusive cumsum)
    float* qf = sm + 2 * L;    // q_f -> Q_f
    float* qb = sm + 3 * L;    // q_b -> Q_b
    __shared__ float wred[32];

    const int   b    = blockIdx.x;
    const int   tid  = threadIdx.x;
    const float k    = kern[0];
    const float* gin = conc + (size_t)b * L * F;

    // ---- Phase 1: load, compute bcd + rowsum ----
#pragma unroll
    for (int ii = 0; ii < CH; ii++) {
        int i = tid + ii * NT;
        const float* p = gin + (size_t)i * F;
        float v0 = p[0];
        float rs = v0;
#pragma unroll
        for (int f = 1; f < F; f++) rs += p[f];
        sb[i] = v0;
        sp[i] = rs;
    }
    __syncthreads();

    // ---- Phase 2: P[t] = 1 + inclusive prefix of rowsum ----
    block_scan(sp, wred, 1.0f);
    __syncthreads();

    const float Z1 = sp[L - 1];        // P[L-1]
    const float C2 = Z1 + 1.0f;        // Total + 2 ; S[x] = C2 - P[x-1]

    // ---- Phase 3: build q_f, q_b ----
#pragma unroll
    for (int ii = 0; ii < CH; ii++) {
        int i = tid + ii * NT;
        float bi = sb[i];
        float pf = (i >= 14) ? sp[i - 14] : 1.0f;            // P[i-14], P[<0]=1
        qf[i] = bi * pf;
        float sv = (i + 14 < L) ? (C2 - sp[i + 13]) : 1.0f;  // S[i+14], S[>=L]=1
        qb[i] = bi * sv;
    }
    __syncthreads();

    // ---- Phase 4: prefix-scan q_f and q_b ----
    block_scan(qf, wred, 0.0f);
    __syncthreads();
    block_scan(qb, wred, 0.0f);
    __syncthreads();

    // ---- Phase 5: windows + all 9 output channels (coalesced) ----
    float* outb = out + (size_t)b * F * L;
#pragma unroll
    for (int ii = 0; ii < CH; ii++) {
        int t = tid + ii * NT;
        float bcd = sb[t];

        // W_f[t] = sum_{s=t-75}^{t-16} q_f[s]
        float wf = ((t - 16 >= 0) ? qf[t - 16] : 0.0f)
                 - ((t - 76 >= 0) ? qf[t - 76] : 0.0f);
        // W_b[t] = sum_{s=t+16}^{t+75} q_b[s]
        int hi = t + 75; if (hi > L - 1) hi = L - 1;
        int lo = t + 15; if (lo > L - 1) lo = L - 1;
        float wb = qb[hi] - qb[lo];

        float cf = bcd * k * wf;
        float cb = bcd * k * wb;
        float num = cf * bcd + bcd * cb + bcd * bcd;
        outb[t] = clip01(num / adjv(bcd) / Z1);

        const float* p = gin + (size_t)t * F;
#pragma unroll
        for (int ch = 1; ch < F; ch++) {
            float v = p[ch];
            outb[(size_t)ch * L + t] = clip01((v * v) / adjv(v) / Z1);
        }
    }
}

extern "C" void kernel_launch(void* const* d_in, const int* in_sizes, int n_in,
                              void* d_out, int out_size) {
    const float* conc = (const float*)d_in[0];
    const float* kern = (const float*)d_in[1];
    float* out = (float*)d_out;
    const int B = in_sizes[0] / (L * F);

    const size_t smem = (size_t)4 * L * sizeof(float);  // 128 KB
    cudaFuncSetAttribute(kenneth_kernel,
                         cudaFuncAttributeMaxDynamicSharedMemorySize, (int)smem);
    kenneth_kernel<<<B, NT, smem>>>(conc, kern, out);
}